// round 2
// baseline (speedup 1.0000x reference)
#include <cuda_runtime.h>

// Fused pre-norm attention-downsampling:
//   out[b,s,:] = q[b,s,:] + sum_f (LN(q[b,s]) . LN(k[b,4s+f])) * LN(v[b,4s+f])
// B=4, Sq=2048, Skv=8192, D=1024, factor=4. Pure streaming / HBM-bound.

#define DD 1024
#define NTHREADS 256
#define NWARPS 8
#define FACTOR 4
#define LN_EPS 1e-5f

template <int N>
__device__ __forceinline__ void block_reduce(float (&val)[N], float* sm) {
#pragma unroll
    for (int i = 0; i < N; i++) {
#pragma unroll
        for (int o = 16; o; o >>= 1)
            val[i] += __shfl_xor_sync(0xffffffffu, val[i], o);
    }
    const int warp = threadIdx.x >> 5;
    const int lane = threadIdx.x & 31;
    __syncthreads();  // protect smem from previous reduction's readers
    if (lane == 0) {
#pragma unroll
        for (int i = 0; i < N; i++) sm[warp * N + i] = val[i];
    }
    __syncthreads();
#pragma unroll
    for (int i = 0; i < N; i++) {
        float t = 0.f;
#pragma unroll
        for (int w = 0; w < NWARPS; w++) t += sm[w * N + i];
        val[i] = t;
    }
}

__global__ __launch_bounds__(NTHREADS) void attn_ds_kernel(
    const float* __restrict__ q, const float* __restrict__ k,
    const float* __restrict__ v, const float* __restrict__ lnw,
    const float* __restrict__ lnb, float* __restrict__ out) {
    __shared__ float sm[NWARPS * 3];

    const int bid = blockIdx.x;          // 0..8191  (= b*2048 + s)
    const int b = bid >> 11;
    const int s = bid & 2047;
    const int t = threadIdx.x;
    const float invD = 1.0f / (float)DD;

    const float4* q4 = (const float4*)(q + (size_t)bid * DD);
    const size_t kvoff = ((size_t)b * 8192 + (size_t)s * FACTOR) * DD;
    const float4* k4 = (const float4*)(k + kvoff);
    const float4* v4 = (const float4*)(v + kvoff);

    // Front-batched loads: 11 independent 128-bit loads per thread (high MLP).
    float4 qv = q4[t];
    float4 wv = ((const float4*)lnw)[t];
    float4 bv = ((const float4*)lnb)[t];
    float4 kr[FACTOR], vr[FACTOR];
#pragma unroll
    for (int f = 0; f < FACTOR; f++) {
        kr[f] = k4[f * (DD / 4) + t];
        vr[f] = v4[f * (DD / 4) + t];
    }

    // ---- LN(q) ----
    float r2[2];
    r2[0] = qv.x + qv.y + qv.z + qv.w;
    r2[1] = qv.x * qv.x + qv.y * qv.y + qv.z * qv.z + qv.w * qv.w;
    block_reduce<2>(r2, sm);
    float mu = r2[0] * invD;
    float rs = rsqrtf(fmaf(-mu, mu, r2[1] * invD) + LN_EPS);
    float4 qn;
    qn.x = fmaf((qv.x - mu) * rs, wv.x, bv.x);
    qn.y = fmaf((qv.y - mu) * rs, wv.y, bv.y);
    qn.z = fmaf((qv.z - mu) * rs, wv.z, bv.z);
    qn.w = fmaf((qv.w - mu) * rs, wv.w, bv.w);

    float4 acc = qv;  // residual

#pragma unroll
    for (int f = 0; f < FACTOR; f++) {
        const float4 kv = kr[f];
        const float4 vv = vr[f];

        // ---- k statistics ----
        float s2[2];
        s2[0] = kv.x + kv.y + kv.z + kv.w;
        s2[1] = kv.x * kv.x + kv.y * kv.y + kv.z * kv.z + kv.w * kv.w;
        block_reduce<2>(s2, sm);
        const float muk = s2[0] * invD;
        const float rsk = rsqrtf(fmaf(-muk, muk, s2[1] * invD) + LN_EPS);

        // ---- fused: qn.kn dot partial + v statistics (one 3-way reduction) ----
        float r3[3];
        {
            const float knx = fmaf((kv.x - muk) * rsk, wv.x, bv.x);
            const float kny = fmaf((kv.y - muk) * rsk, wv.y, bv.y);
            const float knz = fmaf((kv.z - muk) * rsk, wv.z, bv.z);
            const float knw = fmaf((kv.w - muk) * rsk, wv.w, bv.w);
            r3[0] = knx * qn.x + kny * qn.y + knz * qn.z + knw * qn.w;
        }
        r3[1] = vv.x + vv.y + vv.z + vv.w;
        r3[2] = vv.x * vv.x + vv.y * vv.y + vv.z * vv.z + vv.w * vv.w;
        block_reduce<3>(r3, sm);

        const float wt = r3[0];
        const float muv = r3[1] * invD;
        const float rsv = rsqrtf(fmaf(-muv, muv, r3[2] * invD) + LN_EPS);

        acc.x = fmaf(wt, fmaf((vv.x - muv) * rsv, wv.x, bv.x), acc.x);
        acc.y = fmaf(wt, fmaf((vv.y - muv) * rsv, wv.y, bv.y), acc.y);
        acc.z = fmaf(wt, fmaf((vv.z - muv) * rsv, wv.z, bv.z), acc.z);
        acc.w = fmaf(wt, fmaf((vv.w - muv) * rsv, wv.w, bv.w), acc.w);
    }

    ((float4*)(out + (size_t)bid * DD))[t] = acc;
}

extern "C" void kernel_launch(void* const* d_in, const int* in_sizes, int n_in,
                              void* d_out, int out_size) {
    const float* q   = (const float*)d_in[0];  // query   [4,2048,1024]
    const float* k   = (const float*)d_in[1];  // key     [4,8192,1024]
    const float* v   = (const float*)d_in[2];  // value   [4,8192,1024]
    const float* lnw = (const float*)d_in[3];  // ln_weight [1024]
    const float* lnb = (const float*)d_in[4];  // ln_bias   [1024]
    float* out = (float*)d_out;                // [4,2048,1024]

    attn_ds_kernel<<<4 * 2048, NTHREADS>>>(q, k, v, lnw, lnb, out);
}

// round 4
// speedup vs baseline: 1.4730x; 1.4730x over previous
#include <cuda_runtime.h>

// Fused pre-norm attention-downsampling:
//   out[b,s,:] = q[b,s,:] + sum_f (LN(q[b,s]) . LN(k[b,4s+f])) * LN(v[b,4s+f])
// B=4, Sq=2048, Skv=8192, D=1024, factor=4.  HBM-streaming kernel.
// R2: batch 9 block-reductions into 2 (barriers 18 -> 4, LDS ~176 -> ~25/thread).

#define DD 1024
#define NTHREADS 256
#define NWARPS 8
#define FACTOR 4
#define LN_EPS 1e-5f
#define SM_BCAST 96   // broadcast region starts after 8 warps * 12 max values

// Batched block reduction of N values. 2 barriers.
// sm must have at least SM_BCAST + N floats.
template <int N>
__device__ __forceinline__ void block_reduce(float (&val)[N], float* sm) {
#pragma unroll
    for (int i = 0; i < N; i++) {
#pragma unroll
        for (int o = 16; o; o >>= 1)
            val[i] += __shfl_xor_sync(0xffffffffu, val[i], o);
    }
    const int warp = threadIdx.x >> 5;
    const int lane = threadIdx.x & 31;
    if (lane == 0) {
#pragma unroll
        for (int i = 0; i < N; i++) sm[warp * N + i] = val[i];
    }
    __syncthreads();
    if (threadIdx.x < N) {
        float t = 0.f;
#pragma unroll
        for (int w = 0; w < NWARPS; w++) t += sm[w * N + threadIdx.x];
        sm[SM_BCAST + threadIdx.x] = t;
    }
    __syncthreads();
#pragma unroll
    for (int i = 0; i < N; i++) val[i] = sm[SM_BCAST + i];
}

__device__ __forceinline__ float hsum(const float4 a) {
    return (a.x + a.y) + (a.z + a.w);
}
__device__ __forceinline__ float hsq(const float4 a) {
    return (a.x * a.x + a.y * a.y) + (a.z * a.z + a.w * a.w);
}

__global__ __launch_bounds__(NTHREADS) void attn_ds_kernel(
    const float* __restrict__ q, const float* __restrict__ k,
    const float* __restrict__ v, const float* __restrict__ lnw,
    const float* __restrict__ lnb, float* __restrict__ out) {
    __shared__ float sm[SM_BCAST + 12];

    const int bid = blockIdx.x;          // b*2048 + s
    const int b = bid >> 11;
    const int s = bid & 2047;
    const int t = threadIdx.x;
    const float invD = 1.0f / (float)DD;

    const float4* q4 = (const float4*)(q + (size_t)bid * DD);
    const size_t kvoff = ((size_t)b * 8192 + (size_t)s * FACTOR) * DD;
    const float4* k4 = (const float4*)(k + kvoff);
    const float4* v4 = (const float4*)(v + kvoff);

    // Front-batched loads: 11 independent 128-bit loads/thread.
    float4 qv = q4[t];
    float4 wv = ((const float4*)lnw)[t];
    float4 bv = ((const float4*)lnb)[t];
    float4 kr[FACTOR], vr[FACTOR];
#pragma unroll
    for (int f = 0; f < FACTOR; f++) {
        kr[f] = k4[f * (DD / 4) + t];
        vr[f] = v4[f * (DD / 4) + t];
    }

    // ---- Phase 1: one batched reduction of 10 stats ----
    float r1[10];
    r1[0] = hsum(qv);
    r1[1] = hsq(qv);
#pragma unroll
    for (int f = 0; f < FACTOR; f++) {
        r1[2 + 2 * f] = hsum(kr[f]);
        r1[3 + 2 * f] = hsq(kr[f]);
    }
    block_reduce<10>(r1, sm);

    const float mu = r1[0] * invD;
    const float rs = rsqrtf(fmaf(-mu, mu, r1[1] * invD) + LN_EPS);
    float4 qn;
    qn.x = fmaf((qv.x - mu) * rs, wv.x, bv.x);
    qn.y = fmaf((qv.y - mu) * rs, wv.y, bv.y);
    qn.z = fmaf((qv.z - mu) * rs, wv.z, bv.z);
    qn.w = fmaf((qv.w - mu) * rs, wv.w, bv.w);

    // ---- Phase 2: one batched reduction of 12 values ----
    float r2[12];
#pragma unroll
    for (int f = 0; f < FACTOR; f++) {
        const float muk = r1[2 + 2 * f] * invD;
        const float rsk =
            rsqrtf(fmaf(-muk, muk, r1[3 + 2 * f] * invD) + LN_EPS);
        const float4 kv = kr[f];
        const float knx = fmaf((kv.x - muk) * rsk, wv.x, bv.x);
        const float kny = fmaf((kv.y - muk) * rsk, wv.y, bv.y);
        const float knz = fmaf((kv.z - muk) * rsk, wv.z, bv.z);
        const float knw = fmaf((kv.w - muk) * rsk, wv.w, bv.w);
        r2[f] = (knx * qn.x + kny * qn.y) + (knz * qn.z + knw * qn.w);
        r2[4 + f] = hsum(vr[f]);
        r2[8 + f] = hsq(vr[f]);
    }
    block_reduce<12>(r2, sm);

    // ---- Epilogue: residual + weighted LN(v) ----
#pragma unroll
    for (int f = 0; f < FACTOR; f++) {
        const float wt = r2[f];
        const float muv = r2[4 + f] * invD;
        const float rsv = rsqrtf(fmaf(-muv, muv, r2[8 + f] * invD) + LN_EPS);
        const float4 vv = vr[f];
        qv.x = fmaf(wt, fmaf((vv.x - muv) * rsv, wv.x, bv.x), qv.x);
        qv.y = fmaf(wt, fmaf((vv.y - muv) * rsv, wv.y, bv.y), qv.y);
        qv.z = fmaf(wt, fmaf((vv.z - muv) * rsv, wv.z, bv.z), qv.z);
        qv.w = fmaf(wt, fmaf((vv.w - muv) * rsv, wv.w, bv.w), qv.w);
    }

    ((float4*)(out + (size_t)bid * DD))[t] = qv;
}

extern "C" void kernel_launch(void* const* d_in, const int* in_sizes, int n_in,
                              void* d_out, int out_size) {
    const float* q   = (const float*)d_in[0];  // query     [4,2048,1024]
    const float* k   = (const float*)d_in[1];  // key       [4,8192,1024]
    const float* v   = (const float*)d_in[2];  // value     [4,8192,1024]
    const float* lnw = (const float*)d_in[3];  // ln_weight [1024]
    const float* lnb = (const float*)d_in[4];  // ln_bias   [1024]
    float* out = (float*)d_out;                // [4,2048,1024]

    attn_ds_kernel<<<4 * 2048, NTHREADS>>>(q, k, v, lnw, lnb, out);
}